// round 7
// baseline (speedup 1.0000x reference)
#include <cuda_runtime.h>
#include <cstdint>
#include <math.h>

#define BB   2
#define SS   2048
#define HHID 2048
#define NHQ  16
#define NKVH 4
#define DDIM 128
#define TTOK (BB*SS)     // 4096
#define PAD_ROWS 4224    // 33 tiles of 128

typedef unsigned long long ull;

// ---------------- packed f32x2 helpers ----------------
__device__ __forceinline__ ull pk2(float x, float y) {
    ull r; asm("mov.b64 %0, {%1,%2};" : "=l"(r) : "f"(x), "f"(y)); return r;
}
__device__ __forceinline__ void upk2(float& x, float& y, ull v) {
    asm("mov.b64 {%0,%1}, %2;" : "=f"(x), "=f"(y) : "l"(v));
}
__device__ __forceinline__ void fma2(ull& d, ull a, ull b) {
    asm("fma.rn.f32x2 %0, %1, %2, %0;" : "+l"(d) : "l"(a), "l"(b));
}
__device__ __forceinline__ ull mul2(ull a, ull b) {
    ull r; asm("mul.rn.f32x2 %0, %1, %2;" : "=l"(r) : "l"(a), "l"(b)); return r;
}

// ---------------- scratch ----------------
__device__ __align__(16) int g_src[PAD_ROWS];   // sorted row -> src token (-1 = pad)
__device__ unsigned g_tiles0_dev;
__device__ __align__(16) float g_q [(size_t)BB*NHQ *SS*DDIM];   // [B][NH][S][D]  (post-RoPE)
__device__ __align__(16) float g_k [(size_t)BB*NKVH*SS*DDIM];   // [B][NKV][S][D] (post-RoPE)
__device__ __align__(16) float g_v [(size_t)BB*NKVH*SS*DDIM];
__device__ __align__(16) float g_ao[(size_t)TTOK*HHID];         // [B][S][NH*D] token order

// ===================== kernel: expert scan / permutation =====================
__global__ __launch_bounds__(1024) void scan_kernel(const int* __restrict__ tt)
{
    __shared__ int wtot[32];
    int tid = threadIdx.x, lane = tid & 31, wid = tid >> 5;
    for (int j = tid; j < PAD_ROWS; j += 1024) g_src[j] = -1;
    __syncthreads();

    int t0 = tid * 4;
    int cs[4];
#pragma unroll
    for (int i = 0; i < 4; i++) cs[i] = tt[t0 + i];
    int loc = cs[0] + cs[1] + cs[2] + cs[3];
    int inc = loc;
#pragma unroll
    for (int o = 1; o < 32; o <<= 1) { int v = __shfl_up_sync(0xffffffffu, inc, o); if (lane >= o) inc += v; }
    if (lane == 31) wtot[wid] = inc;
    __syncthreads();
    if (wid == 0) {
        int v = wtot[lane];
#pragma unroll
        for (int o = 1; o < 32; o <<= 1) { int u = __shfl_up_sync(0xffffffffu, v, o); if (lane >= o) v += u; }
        wtot[lane] = v;
    }
    __syncthreads();
    int total1 = wtot[31];
    int base1  = (wid > 0 ? wtot[wid - 1] : 0) + (inc - loc);
    int n0 = TTOK - total1;
    int tiles0 = (n0 + 127) >> 7;
    if (tid == 0) g_tiles0_dev = (unsigned)tiles0;
    int off1 = tiles0 * 128;
    int run1 = base1;
#pragma unroll
    for (int i = 0; i < 4; i++) {
        int idx = t0 + i;
        int dst = cs[i] ? (off1 + run1) : (idx - run1);
        g_src[dst] = idx;
        run1 += cs[i];
    }
}

// ===================== shared GEMM inner machinery (f32x2, k-tile 32) =====================
// As: transposed A tile [32 k][132 pad], Bs: [32 k][128 n]
__device__ __forceinline__ void gemm_tile_f32x2(
    const float (*As)[132], const float (*Bs)[128], int tx, int ty, ull acc2[8][4])
{
#pragma unroll 8
    for (int kk = 0; kk < 32; kk++) {
        float a[8];
        *(float4*)&a[0] = *(float4*)&As[kk][ty * 8];
        *(float4*)&a[4] = *(float4*)&As[kk][ty * 8 + 4];
        ull av[8];
#pragma unroll
        for (int i = 0; i < 8; i++) av[i] = pk2(a[i], a[i]);
        ulonglong2 b01 = *(ulonglong2*)&Bs[kk][tx * 8];
        ulonglong2 b23 = *(ulonglong2*)&Bs[kk][tx * 8 + 4];
        ull bv[4] = {b01.x, b01.y, b23.x, b23.y};
#pragma unroll
        for (int i = 0; i < 8; i++)
#pragma unroll
            for (int j = 0; j < 4; j++)
                fma2(acc2[i][j], av[i], bv[j]);
    }
}

// ===================== kernel: QKV projection (f32x2, sorted experts) + bias + RoPE =====================
// grid (33, 24): ct 0..15 Q-heads, 16..19 K-heads, 20..23 V-heads. block 256.
__global__ __launch_bounds__(256) void qkv_kernel(
    const float* __restrict__ hs,
    const float* __restrict__ Wq, const float* __restrict__ bq,
    const float* __restrict__ Wk, const float* __restrict__ bk,
    const float* __restrict__ Wv, const float* __restrict__ bv,
    const float* __restrict__ cosp, const float* __restrict__ sinp)
{
    const int rt = blockIdx.x, ct = blockIdx.y;
    const int tiles0 = (int)g_tiles0_dev;
    const int e = (rt < tiles0) ? 0 : 1;
    const int m0 = rt * 128;

    const float* W; const float* bias; int nstr, n0, which, head;
    if (ct < 16)      { W = Wq; bias = bq; nstr = 2048; n0 = ct * 128;        which = 0; head = ct;      }
    else if (ct < 20) { W = Wk; bias = bk; nstr = 512;  n0 = (ct - 16) * 128; which = 1; head = ct - 16; }
    else              { W = Wv; bias = bv; nstr = 512;  n0 = (ct - 20) * 128; which = 2; head = ct - 20; }
    W    += (size_t)e * 2048 * nstr;
    bias += (size_t)e * nstr;

    __shared__ float As[32][132];
    __shared__ float Bs[32][128];

    const int tid = threadIdx.x;
    const int tx = tid & 15, ty = tid >> 4;

    const int arow0 = tid >> 2, kc = tid & 3;
    const int asrc0 = g_src[m0 + arow0];
    const int asrc1 = g_src[m0 + arow0 + 64];

    ull acc2[8][4];
#pragma unroll
    for (int i = 0; i < 8; i++)
#pragma unroll
        for (int j = 0; j < 4; j++) acc2[i][j] = 0ull;

    for (int k0 = 0; k0 < 2048; k0 += 32) {
#pragma unroll
        for (int half = 0; half < 2; half++) {
            int g = kc + half * 4;
            float4 v0 = make_float4(0.f, 0.f, 0.f, 0.f);
            float4 v1 = make_float4(0.f, 0.f, 0.f, 0.f);
            if (asrc0 >= 0) v0 = *(const float4*)&hs[(size_t)asrc0 * 2048 + k0 + g * 4];
            if (asrc1 >= 0) v1 = *(const float4*)&hs[(size_t)asrc1 * 2048 + k0 + g * 4];
            As[g * 4 + 0][arow0] = v0.x; As[g * 4 + 1][arow0] = v0.y;
            As[g * 4 + 2][arow0] = v0.z; As[g * 4 + 3][arow0] = v0.w;
            As[g * 4 + 0][arow0 + 64] = v1.x; As[g * 4 + 1][arow0 + 64] = v1.y;
            As[g * 4 + 2][arow0 + 64] = v1.z; As[g * 4 + 3][arow0 + 64] = v1.w;
        }
#pragma unroll
        for (int it = 0; it < 4; it++) {
            int f = tid + it * 256;
            int kr = f >> 5, nc = f & 31;
            *(float4*)&Bs[kr][nc * 4] = *(const float4*)&W[(size_t)(k0 + kr) * nstr + n0 + nc * 4];
        }
        __syncthreads();
        gemm_tile_f32x2(As, Bs, tx, ty, acc2);
        __syncthreads();
    }

    // ---- epilogue: unpack + bias + fused RoPE (shfl pair) + scatter ----
    const float* bp = bias + n0;
#pragma unroll
    for (int i = 0; i < 8; i++) {
        const int row = m0 + ty * 8 + i;
        const int src = g_src[row];
        const int sEff = (src >= 0) ? src : 0;
        const int b = sEff >> 11, s = sEff & 2047;

        float v8[8];
#pragma unroll
        for (int j = 0; j < 4; j++) upk2(v8[2 * j], v8[2 * j + 1], acc2[i][j]);
#pragma unroll
        for (int j = 0; j < 8; j++) v8[j] += __ldg(&bp[tx * 8 + j]);

        if (which < 2) {
            float p8[8];
#pragma unroll
            for (int j = 0; j < 8; j++) p8[j] = __shfl_xor_sync(0xffffffffu, v8[j], 8);
            const size_t cb = ((size_t)(b * 2048 + s)) * 128;
#pragma unroll
            for (int j = 0; j < 8; j++) {
                int col = tx * 8 + j;
                float c  = __ldg(&cosp[cb + col]);
                float sn = __ldg(&sinp[cb + col]);
                v8[j] = (tx < 8) ? (v8[j] * c - p8[j] * sn)
                                 : (v8[j] * c + p8[j] * sn);
            }
        }

        if (src >= 0) {
            float* dst;
            if (which == 0)      dst = &g_q[((size_t)((b * NHQ  + head) * SS + s)) * DDIM + tx * 8];
            else if (which == 1) dst = &g_k[((size_t)((b * NKVH + head) * SS + s)) * DDIM + tx * 8];
            else                 dst = &g_v[((size_t)((b * NKVH + head) * SS + s)) * DDIM + tx * 8];
            *(float4*)&dst[0] = make_float4(v8[0], v8[1], v8[2], v8[3]);
            *(float4*)&dst[4] = make_float4(v8[4], v8[5], v8[6], v8[7]);
        }
    }
}

// ===================== kernel: causal flash attention (f32x2 inner loops) =====================
// grid: (16 q-tiles [reversed], B*NH=32). BQ=128, BKV=64. smem 160KB.
__global__ __launch_bounds__(256) void attn_kernel()
{
    extern __shared__ float sm[];
    float* sQt = sm;               // [128 d][128 r]
    float* sKt = sm + 16384;       // [128 d][64 c]
    float* sV  = sm + 24576;       // [64 c][128 d]
    float* sPt = sm + 32768;       // [64 c][128 r]

    const int bh = blockIdx.y;
    const int b = bh >> 4, h = bh & 15, hk = h >> 2;
    const int qt = 15 - blockIdx.x;
    const int q0 = qt * 128;
    const float* Q = g_q + (size_t)(b * NHQ  + h ) * SS * DDIM;
    const float* K = g_k + (size_t)(b * NKVH + hk) * SS * DDIM;
    const float* V = g_v + (size_t)(b * NKVH + hk) * SS * DDIM;

    const int tid = threadIdx.x;
    const int tx = tid & 15, ty = tid >> 4;

#pragma unroll
    for (int it = 0; it < 16; it++) {
        int f = tid + it * 256;
        int r = f >> 5, dc = f & 31;
        float4 v = *(const float4*)&Q[(size_t)(q0 + r) * DDIM + dc * 4];
        sQt[(dc * 4 + 0) * 128 + r] = v.x;
        sQt[(dc * 4 + 1) * 128 + r] = v.y;
        sQt[(dc * 4 + 2) * 128 + r] = v.z;
        sQt[(dc * 4 + 3) * 128 + r] = v.w;
    }

    ull accO2[4][8];               // row pairs (2p,2p+1) x 8 cols
    float mrow[8], lrow[8];
#pragma unroll
    for (int p = 0; p < 4; p++)
#pragma unroll
        for (int j = 0; j < 8; j++) accO2[p][j] = 0ull;
#pragma unroll
    for (int i = 0; i < 8; i++) { mrow[i] = -1e30f; lrow[i] = 0.f; }

    const float scale = 0.08838834764831845f;
    const int ktiles = 2 * qt + 2;

    for (int kt = 0; kt < ktiles; kt++) {
        const int k0 = kt * 64;
        __syncthreads();
#pragma unroll
        for (int it = 0; it < 8; it++) {
            int f = tid + it * 256;
            int c = f >> 5, dc = f & 31;
            float4 v = *(const float4*)&K[(size_t)(k0 + c) * DDIM + dc * 4];
            sKt[(dc * 4 + 0) * 64 + c] = v.x;
            sKt[(dc * 4 + 1) * 64 + c] = v.y;
            sKt[(dc * 4 + 2) * 64 + c] = v.z;
            sKt[(dc * 4 + 3) * 64 + c] = v.w;
        }
#pragma unroll
        for (int it = 0; it < 8; it++) {
            int f = tid + it * 256;
            int c = f >> 5, dc = f & 31;
            *(float4*)&sV[c * 128 + dc * 4] = *(const float4*)&V[(size_t)(k0 + c) * DDIM + dc * 4];
        }
        __syncthreads();

        // ---- S = Q K^T  (row-pair packed) ----
        ull sc2[4][4];
#pragma unroll
        for (int p = 0; p < 4; p++)
#pragma unroll
            for (int j = 0; j < 4; j++) sc2[p][j] = 0ull;
#pragma unroll 8
        for (int d = 0; d < 128; d++) {
            ulonglong2 q01 = *(ulonglong2*)&sQt[d * 128 + ty * 8];
            ulonglong2 q23 = *(ulonglong2*)&sQt[d * 128 + ty * 8 + 4];
            ull qp[4] = {q01.x, q01.y, q23.x, q23.y};
            float kf[4];
            *(float4*)&kf[0] = *(float4*)&sKt[d * 64 + tx * 4];
            ull kp[4];
#pragma unroll
            for (int j = 0; j < 4; j++) kp[j] = pk2(kf[j], kf[j]);
#pragma unroll
            for (int p = 0; p < 4; p++)
#pragma unroll
                for (int j = 0; j < 4; j++)
                    fma2(sc2[p][j], qp[p], kp[j]);
        }
        // ---- unpack, scale, mask ----
        float sc[8][4];
#pragma unroll
        for (int p = 0; p < 4; p++)
#pragma unroll
            for (int j = 0; j < 4; j++) upk2(sc[2 * p][j], sc[2 * p + 1][j], sc2[p][j]);
#pragma unroll
        for (int i = 0; i < 8; i++)
#pragma unroll
            for (int j = 0; j < 4; j++) sc[i][j] *= scale;
        if (k0 + 63 > q0) {
#pragma unroll
            for (int i = 0; i < 8; i++)
#pragma unroll
                for (int j = 0; j < 4; j++)
                    if (k0 + tx * 4 + j > q0 + ty * 8 + i) sc[i][j] = -1e30f;
        }
        // ---- online softmax ----
        float alpha[8];
#pragma unroll
        for (int i = 0; i < 8; i++) {
            float mx = fmaxf(fmaxf(sc[i][0], sc[i][1]), fmaxf(sc[i][2], sc[i][3]));
#pragma unroll
            for (int o = 1; o < 16; o <<= 1) mx = fmaxf(mx, __shfl_xor_sync(0xffffffffu, mx, o));
            float mn = fmaxf(mrow[i], mx);
            alpha[i] = __expf(mrow[i] - mn);
            mrow[i] = mn;
            float rs = 0.f;
#pragma unroll
            for (int j = 0; j < 4; j++) { float p = __expf(sc[i][j] - mn); sc[i][j] = p; rs += p; }
#pragma unroll
            for (int o = 1; o < 16; o <<= 1) rs += __shfl_xor_sync(0xffffffffu, rs, o);
            lrow[i] = lrow[i] * alpha[i] + rs;
        }
#pragma unroll
        for (int p = 0; p < 4; p++) {
            ull aph = pk2(alpha[2 * p], alpha[2 * p + 1]);
#pragma unroll
            for (int j = 0; j < 8; j++) accO2[p][j] = mul2(accO2[p][j], aph);
        }
        // ---- stage P transposed ----
#pragma unroll
        for (int i = 0; i < 8; i++)
#pragma unroll
            for (int j = 0; j < 4; j++)
                sPt[(tx * 4 + j) * 128 + ty * 8 + i] = sc[i][j];
        __syncthreads();
        // ---- O += P V  (row-pair packed) ----
#pragma unroll 4
        for (int c = 0; c < 64; c++) {
            ulonglong2 p01 = *(ulonglong2*)&sPt[c * 128 + ty * 8];
            ulonglong2 p23 = *(ulonglong2*)&sPt[c * 128 + ty * 8 + 4];
            ull pp[4] = {p01.x, p01.y, p23.x, p23.y};
            float vf[8];
            *(float4*)&vf[0] = *(float4*)&sV[c * 128 + tx * 8];
            *(float4*)&vf[4] = *(float4*)&sV[c * 128 + tx * 8 + 4];
            ull vp[8];
#pragma unroll
            for (int j = 0; j < 8; j++) vp[j] = pk2(vf[j], vf[j]);
#pragma unroll
            for (int p = 0; p < 4; p++)
#pragma unroll
                for (int j = 0; j < 8; j++)
                    fma2(accO2[p][j], pp[p], vp[j]);
        }
    }

    // ---- epilogue: normalize, write token-order [B][S][NH*D] ----
#pragma unroll
    for (int i = 0; i < 8; i++) {
        float inv = 1.f / lrow[i];
        int srow = q0 + ty * 8 + i;
        float o8[8];
#pragma unroll
        for (int j = 0; j < 8; j++) {
            float lo, hi; upk2(lo, hi, accO2[i >> 1][j]);
            o8[j] = ((i & 1) ? hi : lo) * inv;
        }
        float* dst = &g_ao[(size_t)(b * SS + srow) * HHID + h * DDIM + tx * 8];
        *(float4*)&dst[0] = make_float4(o8[0], o8[1], o8[2], o8[3]);
        *(float4*)&dst[4] = make_float4(o8[4], o8[5], o8[6], o8[7]);
    }
}

// ===================== kernel: O projection (f32x2, sorted experts) =====================
// grid (33, 16). block 256.
__global__ __launch_bounds__(256) void oproj_kernel(
    const float* __restrict__ Wo, float* __restrict__ out)
{
    const int rt = blockIdx.x, ct = blockIdx.y;
    const int tiles0 = (int)g_tiles0_dev;
    const int e = (rt < tiles0) ? 0 : 1;
    const int m0 = rt * 128, n0 = ct * 128;
    const float* W = Wo + (size_t)e * 2048 * 2048;

    __shared__ float As[32][132];
    __shared__ float Bs[32][128];

    const int tid = threadIdx.x;
    const int tx = tid & 15, ty = tid >> 4;

    const int arow0 = tid >> 2, kc = tid & 3;
    const int asrc0 = g_src[m0 + arow0];
    const int asrc1 = g_src[m0 + arow0 + 64];

    ull acc2[8][4];
#pragma unroll
    for (int i = 0; i < 8; i++)
#pragma unroll
        for (int j = 0; j < 4; j++) acc2[i][j] = 0ull;

    for (int k0 = 0; k0 < 2048; k0 += 32) {
#pragma unroll
        for (int half = 0; half < 2; half++) {
            int g = kc + half * 4;
            float4 v0 = make_float4(0.f, 0.f, 0.f, 0.f);
            float4 v1 = make_float4(0.f, 0.f, 0.f, 0.f);
            if (asrc0 >= 0) v0 = *(const float4*)&g_ao[(size_t)asrc0 * 2048 + k0 + g * 4];
            if (asrc1 >= 0) v1 = *(const float4*)&g_ao[(size_t)asrc1 * 2048 + k0 + g * 4];
            As[g * 4 + 0][arow0] = v0.x; As[g * 4 + 1][arow0] = v0.y;
            As[g * 4 + 2][arow0] = v0.z; As[g * 4 + 3][arow0] = v0.w;
            As[g * 4 + 0][arow0 + 64] = v1.x; As[g * 4 + 1][arow0 + 64] = v1.y;
            As[g * 4 + 2][arow0 + 64] = v1.z; As[g * 4 + 3][arow0 + 64] = v1.w;
        }
#pragma unroll
        for (int it = 0; it < 4; it++) {
            int f = tid + it * 256;
            int kr = f >> 5, nc = f & 31;
            *(float4*)&Bs[kr][nc * 4] = *(const float4*)&W[(size_t)(k0 + kr) * 2048 + n0 + nc * 4];
        }
        __syncthreads();
        gemm_tile_f32x2(As, Bs, tx, ty, acc2);
        __syncthreads();
    }

#pragma unroll
    for (int i = 0; i < 8; i++) {
        const int src = g_src[m0 + ty * 8 + i];
        if (src >= 0) {
            float v8[8];
#pragma unroll
            for (int j = 0; j < 4; j++) upk2(v8[2 * j], v8[2 * j + 1], acc2[i][j]);
            float* dst = &out[(size_t)src * 2048 + n0 + tx * 8];
            *(float4*)&dst[0] = make_float4(v8[0], v8[1], v8[2], v8[3]);
            *(float4*)&dst[4] = make_float4(v8[4], v8[5], v8[6], v8[7]);
        }
    }
}

// =====================================================================
extern "C" void kernel_launch(void* const* d_in, const int* in_sizes, int n_in,
                              void* d_out, int out_size)
{
    const float* hs   = (const float*)d_in[0];
    const int*   tt   = (const int*)  d_in[1];
    const float* cosp = (const float*)d_in[2];
    const float* sinp = (const float*)d_in[3];
    const float* Wq   = (const float*)d_in[4];
    const float* bq   = (const float*)d_in[5];
    const float* Wk   = (const float*)d_in[6];
    const float* bk   = (const float*)d_in[7];
    const float* Wv   = (const float*)d_in[8];
    const float* bv   = (const float*)d_in[9];
    const float* Wo   = (const float*)d_in[10];
    float* out = (float*)d_out;

    cudaFuncSetAttribute(attn_kernel, cudaFuncAttributeMaxDynamicSharedMemorySize, 163840);

    scan_kernel<<<1, 1024>>>(tt);
    qkv_kernel<<<dim3(33, 24), 256>>>(hs, Wq, bq, Wk, bk, Wv, bv, cosp, sinp);
    attn_kernel<<<dim3(16, 32), 256, 163840>>>();
    oproj_kernel<<<dim3(33, 16), 256>>>(Wo, out);
}

// round 8
// speedup vs baseline: 1.5761x; 1.5761x over previous
#include <cuda_runtime.h>
#include <cuda_bf16.h>
#include <cstdint>
#include <math.h>

#define BB   2
#define SS   2048
#define HHID 2048
#define NHQ  16
#define NKVH 4
#define DDIM 128
#define TTOK (BB*SS)     // 4096
#define PAD_ROWS 4224    // 33 tiles of 128

// ---------------- scratch (kept small: ~58MB, same as Round 6) ----------------
__device__ __align__(16) int g_src[PAD_ROWS];   // sorted row -> src token (-1 = pad)
__device__ unsigned g_tiles0_dev;
__device__ __align__(16) float g_q [(size_t)BB*NHQ *SS*DDIM];   // [B][NH][S][D]  (post-RoPE)
__device__ __align__(16) float g_k [(size_t)BB*NKVH*SS*DDIM];   // [B][NKV][S][D] (post-RoPE)
__device__ __align__(16) float g_v [(size_t)BB*NKVH*SS*DDIM];
__device__ __align__(16) float g_ao[(size_t)TTOK*HHID];         // [B][S][NH*D] token order

// ---------------- helpers ----------------
__device__ __forceinline__ void mma16816(float* d, const uint32_t* a, const uint32_t* b) {
    asm volatile("mma.sync.aligned.m16n8k16.row.col.f32.bf16.bf16.f32 "
        "{%0,%1,%2,%3}, {%4,%5,%6,%7}, {%8,%9}, {%0,%1,%2,%3};"
        : "+f"(d[0]), "+f"(d[1]), "+f"(d[2]), "+f"(d[3])
        : "r"(a[0]), "r"(a[1]), "r"(a[2]), "r"(a[3]), "r"(b[0]), "r"(b[1]));
}
__device__ __forceinline__ uint32_t pkbf(float x, float y) {
    __nv_bfloat16 hx = __float2bfloat16(x), hy = __float2bfloat16(y);
    return (uint32_t)__bfloat16_as_ushort(hx) | ((uint32_t)__bfloat16_as_ushort(hy) << 16);
}
__device__ __forceinline__ void split2(float x, float y, uint32_t& hi, uint32_t& lo) {
    __nv_bfloat16 hx = __float2bfloat16(x), hy = __float2bfloat16(y);
    float rx = x - __bfloat162float(hx), ry = y - __bfloat162float(hy);
    hi = (uint32_t)__bfloat16_as_ushort(hx) | ((uint32_t)__bfloat16_as_ushort(hy) << 16);
    lo = (uint32_t)__bfloat16_as_ushort(__float2bfloat16(rx))
       | ((uint32_t)__bfloat16_as_ushort(__float2bfloat16(ry)) << 16);
}

// ===================== kernel: expert scan / permutation =====================
__global__ __launch_bounds__(1024) void scan_kernel(const int* __restrict__ tt)
{
    __shared__ int wtot[32];
    int tid = threadIdx.x, lane = tid & 31, wid = tid >> 5;
    for (int j = tid; j < PAD_ROWS; j += 1024) g_src[j] = -1;
    __syncthreads();

    int t0 = tid * 4;
    int cs[4];
#pragma unroll
    for (int i = 0; i < 4; i++) cs[i] = tt[t0 + i];
    int loc = cs[0] + cs[1] + cs[2] + cs[3];
    int inc = loc;
#pragma unroll
    for (int o = 1; o < 32; o <<= 1) { int v = __shfl_up_sync(0xffffffffu, inc, o); if (lane >= o) inc += v; }
    if (lane == 31) wtot[wid] = inc;
    __syncthreads();
    if (wid == 0) {
        int v = wtot[lane];
#pragma unroll
        for (int o = 1; o < 32; o <<= 1) { int u = __shfl_up_sync(0xffffffffu, v, o); if (lane >= o) v += u; }
        wtot[lane] = v;
    }
    __syncthreads();
    int total1 = wtot[31];
    int base1  = (wid > 0 ? wtot[wid - 1] : 0) + (inc - loc);
    int n0 = TTOK - total1;
    int tiles0 = (n0 + 127) >> 7;
    if (tid == 0) g_tiles0_dev = (unsigned)tiles0;
    int off1 = tiles0 * 128;
    int run1 = base1;
#pragma unroll
    for (int i = 0; i < 4; i++) {
        int idx = t0 + i;
        int dst = cs[i] ? (off1 + run1) : (idx - run1);
        g_src[dst] = idx;
        run1 += cs[i];
    }
}

// ===================== kernel: QKV projection (fp32 SIMT, sorted experts) + bias + RoPE =====================
// (unchanged from Round 6 — proven)
__global__ __launch_bounds__(256) void qkv_kernel(
    const float* __restrict__ hs,
    const float* __restrict__ Wq, const float* __restrict__ bq,
    const float* __restrict__ Wk, const float* __restrict__ bk,
    const float* __restrict__ Wv, const float* __restrict__ bv,
    const float* __restrict__ cosp, const float* __restrict__ sinp)
{
    const int rt = blockIdx.x, ct = blockIdx.y;
    const int tiles0 = (int)g_tiles0_dev;
    const int e = (rt < tiles0) ? 0 : 1;
    const int m0 = rt * 128;

    const float* W; const float* bias; int nstr, n0, which, head;
    if (ct < 16)      { W = Wq; bias = bq; nstr = 2048; n0 = ct * 128;        which = 0; head = ct;      }
    else if (ct < 20) { W = Wk; bias = bk; nstr = 512;  n0 = (ct - 16) * 128; which = 1; head = ct - 16; }
    else              { W = Wv; bias = bv; nstr = 512;  n0 = (ct - 20) * 128; which = 2; head = ct - 20; }
    W    += (size_t)e * 2048 * nstr;
    bias += (size_t)e * nstr;

    __shared__ float As[16][132];
    __shared__ float Bs[16][128];

    const int tid = threadIdx.x;
    const int tx = tid & 15, ty = tid >> 4;

    const int arow0 = tid >> 2, kc = tid & 3;
    const int asrc0 = g_src[m0 + arow0];
    const int asrc1 = g_src[m0 + arow0 + 64];

    float acc[8][8];
#pragma unroll
    for (int i = 0; i < 8; i++)
#pragma unroll
        for (int j = 0; j < 8; j++) acc[i][j] = 0.f;

    for (int k0 = 0; k0 < 2048; k0 += 16) {
        {
            float4 v0 = make_float4(0.f, 0.f, 0.f, 0.f);
            float4 v1 = make_float4(0.f, 0.f, 0.f, 0.f);
            if (asrc0 >= 0) v0 = *(const float4*)&hs[(size_t)asrc0 * 2048 + k0 + kc * 4];
            if (asrc1 >= 0) v1 = *(const float4*)&hs[(size_t)asrc1 * 2048 + k0 + kc * 4];
            As[kc * 4 + 0][arow0] = v0.x; As[kc * 4 + 1][arow0] = v0.y;
            As[kc * 4 + 2][arow0] = v0.z; As[kc * 4 + 3][arow0] = v0.w;
            As[kc * 4 + 0][arow0 + 64] = v1.x; As[kc * 4 + 1][arow0 + 64] = v1.y;
            As[kc * 4 + 2][arow0 + 64] = v1.z; As[kc * 4 + 3][arow0 + 64] = v1.w;
        }
#pragma unroll
        for (int it = 0; it < 2; it++) {
            int f = tid + it * 256;
            int kr = f >> 5, nc = f & 31;
            *(float4*)&Bs[kr][nc * 4] = *(const float4*)&W[(size_t)(k0 + kr) * nstr + n0 + nc * 4];
        }
        __syncthreads();
#pragma unroll 8
        for (int kk = 0; kk < 16; kk++) {
            float a[8], b[8];
            *(float4*)&a[0] = *(float4*)&As[kk][ty * 8];
            *(float4*)&a[4] = *(float4*)&As[kk][ty * 8 + 4];
            *(float4*)&b[0] = *(float4*)&Bs[kk][tx * 8];
            *(float4*)&b[4] = *(float4*)&Bs[kk][tx * 8 + 4];
#pragma unroll
            for (int i = 0; i < 8; i++)
#pragma unroll
                for (int j = 0; j < 8; j++)
                    acc[i][j] = fmaf(a[i], b[j], acc[i][j]);
        }
        __syncthreads();
    }

    const float* bp = bias + n0;
#pragma unroll
    for (int i = 0; i < 8; i++) {
        const int row = m0 + ty * 8 + i;
        const int src = g_src[row];
        const int sEff = (src >= 0) ? src : 0;
        const int b = sEff >> 11, s = sEff & 2047;

        float v8[8];
#pragma unroll
        for (int j = 0; j < 8; j++) v8[j] = acc[i][j] + __ldg(&bp[tx * 8 + j]);

        if (which < 2) {
            float p8[8];
#pragma unroll
            for (int j = 0; j < 8; j++) p8[j] = __shfl_xor_sync(0xffffffffu, v8[j], 8);
            const size_t cb = ((size_t)(b * 2048 + s)) * 128;
#pragma unroll
            for (int j = 0; j < 8; j++) {
                int col = tx * 8 + j;
                float c  = __ldg(&cosp[cb + col]);
                float sn = __ldg(&sinp[cb + col]);
                v8[j] = (tx < 8) ? (v8[j] * c - p8[j] * sn)
                                 : (v8[j] * c + p8[j] * sn);
            }
        }

        if (src >= 0) {
            float* dst;
            if (which == 0)      dst = &g_q[((size_t)((b * NHQ  + head) * SS + s)) * DDIM + tx * 8];
            else if (which == 1) dst = &g_k[((size_t)((b * NKVH + head) * SS + s)) * DDIM + tx * 8];
            else                 dst = &g_v[((size_t)((b * NKVH + head) * SS + s)) * DDIM + tx * 8];
            *(float4*)&dst[0] = make_float4(v8[0], v8[1], v8[2], v8[3]);
            *(float4*)&dst[4] = make_float4(v8[4], v8[5], v8[6], v8[7]);
        }
    }
}

// ===================== kernel: causal flash attention (fp32 SIMT, unchanged from Round 6) =====================
__global__ __launch_bounds__(256) void attn_kernel()
{
    extern __shared__ float sm[];
    float* sQt = sm;               // [128 d][128 r]
    float* sKt = sm + 16384;       // [128 d][64 c]
    float* sV  = sm + 24576;       // [64 c][128 d]
    float* sPt = sm + 32768;       // [64 c][128 r]

    const int bh = blockIdx.y;
    const int b = bh >> 4, h = bh & 15, hk = h >> 2;
    const int qt = 15 - blockIdx.x;
    const int q0 = qt * 128;
    const float* Q = g_q + (size_t)(b * NHQ  + h ) * SS * DDIM;
    const float* K = g_k + (size_t)(b * NKVH + hk) * SS * DDIM;
    const float* V = g_v + (size_t)(b * NKVH + hk) * SS * DDIM;

    const int tid = threadIdx.x;
    const int tx = tid & 15, ty = tid >> 4;

#pragma unroll
    for (int it = 0; it < 16; it++) {
        int f = tid + it * 256;
        int r = f >> 5, dc = f & 31;
        float4 v = *(const float4*)&Q[(size_t)(q0 + r) * DDIM + dc * 4];
        sQt[(dc * 4 + 0) * 128 + r] = v.x;
        sQt[(dc * 4 + 1) * 128 + r] = v.y;
        sQt[(dc * 4 + 2) * 128 + r] = v.z;
        sQt[(dc * 4 + 3) * 128 + r] = v.w;
    }

    float accO[8][8];
    float mrow[8], lrow[8];
#pragma unroll
    for (int i = 0; i < 8; i++) {
        mrow[i] = -1e30f; lrow[i] = 0.f;
#pragma unroll
        for (int j = 0; j < 8; j++) accO[i][j] = 0.f;
    }

    const float scale = 0.08838834764831845f;
    const int ktiles = 2 * qt + 2;

    for (int kt = 0; kt < ktiles; kt++) {
        const int k0 = kt * 64;
        __syncthreads();
#pragma unroll
        for (int it = 0; it < 8; it++) {
            int f = tid + it * 256;
            int c = f >> 5, dc = f & 31;
            float4 v = *(const float4*)&K[(size_t)(k0 + c) * DDIM + dc * 4];
            sKt[(dc * 4 + 0) * 64 + c] = v.x;
            sKt[(dc * 4 + 1) * 64 + c] = v.y;
            sKt[(dc * 4 + 2) * 64 + c] = v.z;
            sKt[(dc * 4 + 3) * 64 + c] = v.w;
        }
#pragma unroll
        for (int it = 0; it < 8; it++) {
            int f = tid + it * 256;
            int c = f >> 5, dc = f & 31;
            *(float4*)&sV[c * 128 + dc * 4] = *(const float4*)&V[(size_t)(k0 + c) * DDIM + dc * 4];
        }
        __syncthreads();

        float sc[8][4];
#pragma unroll
        for (int i = 0; i < 8; i++)
#pragma unroll
            for (int j = 0; j < 4; j++) sc[i][j] = 0.f;
#pragma unroll 8
        for (int d = 0; d < 128; d++) {
            float qf[8], kf[4];
            *(float4*)&qf[0] = *(float4*)&sQt[d * 128 + ty * 8];
            *(float4*)&qf[4] = *(float4*)&sQt[d * 128 + ty * 8 + 4];
            *(float4*)&kf[0] = *(float4*)&sKt[d * 64 + tx * 4];
#pragma unroll
            for (int i = 0; i < 8; i++)
#pragma unroll
                for (int j = 0; j < 4; j++)
                    sc[i][j] = fmaf(qf[i], kf[j], sc[i][j]);
        }
#pragma unroll
        for (int i = 0; i < 8; i++)
#pragma unroll
            for (int j = 0; j < 4; j++) sc[i][j] *= scale;
        if (k0 + 63 > q0) {
#pragma unroll
            for (int i = 0; i < 8; i++)
#pragma unroll
                for (int j = 0; j < 4; j++)
                    if (k0 + tx * 4 + j > q0 + ty * 8 + i) sc[i][j] = -1e30f;
        }
#pragma unroll
        for (int i = 0; i < 8; i++) {
            float mx = fmaxf(fmaxf(sc[i][0], sc[i][1]), fmaxf(sc[i][2], sc[i][3]));
#pragma unroll
            for (int o = 1; o < 16; o <<= 1) mx = fmaxf(mx, __shfl_xor_sync(0xffffffffu, mx, o));
            float mn = fmaxf(mrow[i], mx);
            float alpha = __expf(mrow[i] - mn);
            mrow[i] = mn;
            float rs = 0.f;
#pragma unroll
            for (int j = 0; j < 4; j++) { float p = __expf(sc[i][j] - mn); sc[i][j] = p; rs += p; }
#pragma unroll
            for (int o = 1; o < 16; o <<= 1) rs += __shfl_xor_sync(0xffffffffu, rs, o);
            lrow[i] = lrow[i] * alpha + rs;
#pragma unroll
            for (int j = 0; j < 8; j++) accO[i][j] *= alpha;
        }
#pragma unroll
        for (int i = 0; i < 8; i++)
#pragma unroll
            for (int j = 0; j < 4; j++)
                sPt[(tx * 4 + j) * 128 + ty * 8 + i] = sc[i][j];
        __syncthreads();
#pragma unroll 4
        for (int c = 0; c < 64; c++) {
            float pf[8], vf[8];
            *(float4*)&pf[0] = *(float4*)&sPt[c * 128 + ty * 8];
            *(float4*)&pf[4] = *(float4*)&sPt[c * 128 + ty * 8 + 4];
            *(float4*)&vf[0] = *(float4*)&sV[c * 128 + tx * 8];
            *(float4*)&vf[4] = *(float4*)&sV[c * 128 + tx * 8 + 4];
#pragma unroll
            for (int i = 0; i < 8; i++)
#pragma unroll
                for (int j = 0; j < 8; j++)
                    accO[i][j] = fmaf(pf[i], vf[j], accO[i][j]);
        }
    }

#pragma unroll
    for (int i = 0; i < 8; i++) {
        float inv = 1.f / lrow[i];
        int srow = q0 + ty * 8 + i;
        float* dst = &g_ao[(size_t)(b * SS + srow) * HHID + h * DDIM + tx * 8];
        *(float4*)&dst[0] = make_float4(accO[i][0] * inv, accO[i][1] * inv, accO[i][2] * inv, accO[i][3] * inv);
        *(float4*)&dst[4] = make_float4(accO[i][4] * inv, accO[i][5] * inv, accO[i][6] * inv, accO[i][7] * inv);
    }
}

// ===================== kernel: O projection — mma.sync with self-test + SIMT fallback =====================
// grid (33, 16). block 256. dyn smem 40960B.
#define AF(i,k) ((float)(((i)*17 + (k)*5) % 13 - 6))
#define BF(j,k) ((float)(((j)*7 + (k)*3) % 11 - 5))
__global__ __launch_bounds__(256) void oproj_kernel(
    const float* __restrict__ Wo, float* __restrict__ out)
{
    extern __shared__ char sm8[];
    const int rt = blockIdx.x, ct = blockIdx.y;
    const int tiles0 = (int)g_tiles0_dev;
    const int e = (rt < tiles0) ? 0 : 1;
    const int m0 = rt * 128, n0 = ct * 128;
    const float* W = Wo + (size_t)e * 2048 * 2048;

    const int tid = threadIdx.x, lane = tid & 31, wid = tid >> 5;

    // ---- mma.sync self-test (warp 0), bf16 small-int exact ----
    __shared__ int sOK;
    if (tid < 32) {
        const int g = lane >> 2, t = lane & 3;
        uint32_t a[4], b[2];
        float d[4] = {0.f, 0.f, 0.f, 0.f};
        a[0] = pkbf(AF(g,     2*t),     AF(g,     2*t + 1));
        a[1] = pkbf(AF(g + 8, 2*t),     AF(g + 8, 2*t + 1));
        a[2] = pkbf(AF(g,     2*t + 8), AF(g,     2*t + 9));
        a[3] = pkbf(AF(g + 8, 2*t + 8), AF(g + 8, 2*t + 9));
        b[0] = pkbf(BF(g, 2*t),     BF(g, 2*t + 1));
        b[1] = pkbf(BF(g, 2*t + 8), BF(g, 2*t + 9));
        mma16816(d, a, b);
        bool ok = true;
#pragma unroll
        for (int c = 0; c < 4; c++) {
            int row = (c < 2) ? g : g + 8;
            int col = 2*t + (c & 1);
            float ex = 0.f;
            for (int k = 0; k < 16; k++) ex += AF(row, k) * BF(col, k);
            ok &= fabsf(d[c] - ex) < 0.5f;
        }
        unsigned msk = __ballot_sync(0xffffffffu, ok);
        if (lane == 0) sOK = (msk == 0xffffffffu) ? 1 : 0;
    }
    __syncthreads();

    if (sOK) {
        // ================= tensor path: bf16 hi/lo 3-limb mma =================
        char* sAh = sm8;                 // [128 r][40 k] bf16 = 10240 B
        char* sAl = sm8 + 10240;
        char* sBh = sm8 + 20480;         // [128 n][40 k] bf16
        char* sBl = sm8 + 30720;
        const int g = lane >> 2, t = lane & 3;
        const int wm = wid & 1, wn = wid >> 1;
        const int r2 = tid >> 1, kh = tid & 1;
        const int asrc = g_src[m0 + r2];

        float acc[4][4][4];
#pragma unroll
        for (int mt = 0; mt < 4; mt++)
#pragma unroll
            for (int nt = 0; nt < 4; nt++)
#pragma unroll
                for (int c = 0; c < 4; c++) acc[mt][nt][c] = 0.f;

        for (int k0 = 0; k0 < 2048; k0 += 32) {
            // A: gathered g_ao rows, split to hi/lo (16 k per thread)
#pragma unroll
            for (int j = 0; j < 4; j++) {
                float4 v = make_float4(0.f, 0.f, 0.f, 0.f);
                if (asrc >= 0) v = *(const float4*)&g_ao[(size_t)asrc * 2048 + k0 + kh * 16 + j * 4];
                uint32_t h0, l0, h1, l1;
                split2(v.x, v.y, h0, l0);
                split2(v.z, v.w, h1, l1);
                uint32_t off = (uint32_t)(r2 * 40 + kh * 16 + j * 4) * 2;
                *(uint32_t*)(sAh + off)     = h0;  *(uint32_t*)(sAh + off + 4) = h1;
                *(uint32_t*)(sAl + off)     = l0;  *(uint32_t*)(sAl + off + 4) = l1;
            }
            // B: W[k][n] -> B'[n][k] transposed, split hi/lo
#pragma unroll
            for (int it = 0; it < 4; it++) {
                int f = tid + it * 256;
                int kr = f >> 5, nc = f & 31;
                float4 v = *(const float4*)&W[(size_t)(k0 + kr) * 2048 + n0 + nc * 4];
                float xs[4] = {v.x, v.y, v.z, v.w};
#pragma unroll
                for (int j = 0; j < 4; j++) {
                    __nv_bfloat16 hb = __float2bfloat16(xs[j]);
                    __nv_bfloat16 lb = __float2bfloat16(xs[j] - __bfloat162float(hb));
                    int n = nc * 4 + j;
                    ((__nv_bfloat16*)sBh)[n * 40 + kr] = hb;
                    ((__nv_bfloat16*)sBl)[n * 40 + kr] = lb;
                }
            }
            __syncthreads();
#pragma unroll
            for (int ks = 0; ks < 2; ks++) {
                uint32_t ah[4][4], al[4][4], bh[4][2], bl[4][2];
#pragma unroll
                for (int mt = 0; mt < 4; mt++) {
                    uint32_t ro = (uint32_t)((wm * 64 + mt * 16 + g) * 40 + ks * 16 + 2 * t) * 2;
                    ah[mt][0] = *(uint32_t*)(sAh + ro);
                    ah[mt][1] = *(uint32_t*)(sAh + ro + 640);
                    ah[mt][2] = *(uint32_t*)(sAh + ro + 16);
                    ah[mt][3] = *(uint32_t*)(sAh + ro + 656);
                    al[mt][0] = *(uint32_t*)(sAl + ro);
                    al[mt][1] = *(uint32_t*)(sAl + ro + 640);
                    al[mt][2] = *(uint32_t*)(sAl + ro + 16);
                    al[mt][3] = *(uint32_t*)(sAl + ro + 656);
                }
#pragma unroll
                for (int nt = 0; nt < 4; nt++) {
                    uint32_t ro = (uint32_t)((wn * 32 + nt * 8 + g) * 40 + ks * 16 + 2 * t) * 2;
                    bh[nt][0] = *(uint32_t*)(sBh + ro);
                    bh[nt][1] = *(uint32_t*)(sBh + ro + 16);
                    bl[nt][0] = *(uint32_t*)(sBl + ro);
                    bl[nt][1] = *(uint32_t*)(sBl + ro + 16);
                }
#pragma unroll
                for (int mt = 0; mt < 4; mt++)
#pragma unroll
                    for (int nt = 0; nt < 4; nt++) {
                        mma16816(acc[mt][nt], ah[mt], bh[nt]);
                        mma16816(acc[mt][nt], ah[mt], bl[nt]);
                        mma16816(acc[mt][nt], al[mt], bh[nt]);
                    }
            }
            __syncthreads();
        }
        // epilogue: scatter to token order
#pragma unroll
        for (int mt = 0; mt < 4; mt++) {
            int row0 = m0 + wm * 64 + mt * 16 + g;
            int s0 = g_src[row0], s1 = g_src[row0 + 8];
#pragma unroll
            for (int nt = 0; nt < 4; nt++) {
                int col = n0 + wn * 32 + nt * 8 + 2 * t;
                if (s0 >= 0) *(float2*)&out[(size_t)s0 * 2048 + col] = make_float2(acc[mt][nt][0], acc[mt][nt][1]);
                if (s1 >= 0) *(float2*)&out[(size_t)s1 * 2048 + col] = make_float2(acc[mt][nt][2], acc[mt][nt][3]);
            }
        }
    } else {
        // ================= fallback: Round-6 SIMT fp32 path =================
        float (*As)[132] = (float(*)[132])sm8;
        float (*Bs)[128] = (float(*)[128])(sm8 + 16 * 132 * 4);
        const int tx = tid & 15, ty = tid >> 4;
        const int arow0 = tid >> 2, kc = tid & 3;
        const int asrc0 = g_src[m0 + arow0];
        const int asrc1 = g_src[m0 + arow0 + 64];

        float acc[8][8];
#pragma unroll
        for (int i = 0; i < 8; i++)
#pragma unroll
            for (int j = 0; j < 8; j++) acc[i][j] = 0.f;

        for (int k0 = 0; k0 < 2048; k0 += 16) {
            {
                float4 v0 = make_float4(0.f, 0.f, 0.f, 0.f);
                float4 v1 = make_float4(0.f, 0.f, 0.f, 0.f);
                if (asrc0 >= 0) v0 = *(const float4*)&g_ao[(size_t)asrc0 * 2048 + k0 + kc * 4];
                if (asrc1 >= 0) v1 = *(const float4*)&g_ao[(size_t)asrc1 * 2048 + k0 + kc * 4];
                As[kc * 4 + 0][arow0] = v0.x; As[kc * 4 + 1][arow0] = v0.y;
                As[kc * 4 + 2][arow0] = v0.z; As[kc * 4 + 3][arow0] = v0.w;
                As[kc * 4 + 0][arow0 + 64] = v1.x; As[kc * 4 + 1][arow0 + 64] = v1.y;
                As[kc * 4 + 2][arow0 + 64] = v1.z; As[kc * 4 + 3][arow0 + 64] = v1.w;
            }
#pragma unroll
            for (int it = 0; it < 2; it++) {
                int f = tid + it * 256;
                int kr = f >> 5, nc = f & 31;
                *(float4*)&Bs[kr][nc * 4] = *(const float4*)&W[(size_t)(k0 + kr) * 2048 + n0 + nc * 4];
            }
            __syncthreads();
#pragma unroll 8
            for (int kk = 0; kk < 16; kk++) {
                float a[8], b[8];
                *(float4*)&a[0] = *(float4*)&As[kk][ty * 8];
                *(float4*)&a[4] = *(float4*)&As[kk][ty * 8 + 4];
                *(float4*)&b[0] = *(float4*)&Bs[kk][tx * 8];
                *(float4*)&b[4] = *(float4*)&Bs[kk][tx * 8 + 4];
#pragma unroll
                for (int i = 0; i < 8; i++)
#pragma unroll
                    for (int j = 0; j < 8; j++)
                        acc[i][j] = fmaf(a[i], b[j], acc[i][j]);
            }
            __syncthreads();
        }
#pragma unroll
        for (int i = 0; i < 8; i++) {
            const int src = g_src[m0 + ty * 8 + i];
            if (src >= 0) {
                float* dst = &out[(size_t)src * 2048 + n0 + tx * 8];
                *(float4*)&dst[0] = make_float4(acc[i][0], acc[i][1], acc[i][2], acc[i][3]);
                *(float4*)&dst[4] = make_float4(acc[i][4], acc[i][5], acc[i][6], acc[i][7]);
            }
        }
    }
}
#undef AF
#undef BF

// =====================================================================
extern "C" void kernel_launch(void* const* d_in, const int* in_sizes, int n_in,
                              void* d_out, int out_size)
{
    const float* hs   = (const float*)d_in[0];
    const int*   tt   = (const int*)  d_in[1];
    const float* cosp = (const float*)d_in[2];
    const float* sinp = (const float*)d_in[3];
    const float* Wq   = (const float*)d_in[4];
    const float* bq   = (const float*)d_in[5];
    const float* Wk   = (const float*)d_in[6];
    const float* bk   = (const float*)d_in[7];
    const float* Wv   = (const float*)d_in[8];
    const float* bv   = (const float*)d_in[9];
    const float* Wo   = (const float*)d_in[10];
    float* out = (float*)d_out;

    cudaFuncSetAttribute(attn_kernel,  cudaFuncAttributeMaxDynamicSharedMemorySize, 163840);
    cudaFuncSetAttribute(oproj_kernel, cudaFuncAttributeMaxDynamicSharedMemorySize, 49152);

    scan_kernel<<<1, 1024>>>(tt);
    qkv_kernel<<<dim3(33, 24), 256>>>(hs, Wq, bq, Wk, bk, Wv, bv, cosp, sinp);
    attn_kernel<<<dim3(16, 32), 256, 163840>>>();
    oproj_kernel<<<dim3(33, 16), 256, 40960>>>(Wo, out);
}